// round 10
// baseline (speedup 1.0000x reference)
#include <cuda_runtime.h>
#include <math.h>
#include <stdint.h>

#define N_NODES 100000
#define N_EDGES 800000
#define NB_SCAN ((N_NODES + 255) / 256)   // 391

// ---- static device scratch (no allocations allowed) ----
__device__ int   g_is32;                 // 1 if edge_index delivered as int32
__device__ int   g_cnt [N_NODES];
__device__ int   g_off [N_NODES + 1];
__device__ int   g_cur [N_NODES];
__device__ int   g_srcl[N_EDGES];        // sources grouped by dst (CSR)
__device__ float g_dinv[N_NODES];
__device__ float g_h1  [N_NODES * 64];   // layer-1 pre-agg features
__device__ float g_hid [N_NODES * 64];   // relu'd hidden (layer-2 input)
__device__ float g_h2  [N_NODES * 40];   // layer-2 pre-agg features
__device__ int   g_bsum[512];
__device__ int   g_boff[512];

// ---------------------------------------------------------------------------
// zero counters + dtype detection (int64 values < 2^31 have zero high words)
// ---------------------------------------------------------------------------
__global__ void k_init(const unsigned* __restrict__ ei_raw) {
    int i = blockIdx.x * blockDim.x + threadIdx.x;
    if (i < N_NODES) g_cnt[i] = 0;
    if (blockIdx.x == 0 && threadIdx.x < 32) {
        unsigned v = ei_raw[2 * threadIdx.x + 1];
#pragma unroll
        for (int o = 16; o; o >>= 1) v |= __shfl_xor_sync(0xffffffffu, v, o);
        if (threadIdx.x == 0) g_is32 = (v != 0) ? 1 : 0;
    }
}

__device__ __forceinline__ int edge_at(const void* ei, int idx) {
    if (g_is32) return ((const int*)ei)[idx];
    return (int)((const long long*)ei)[idx];
}

// ---------------------------------------------------------------------------
// CSR build
// ---------------------------------------------------------------------------
__global__ void k_count(const void* __restrict__ ei) {
    int e = blockIdx.x * blockDim.x + threadIdx.x;
    if (e >= N_EDGES) return;
    int d = edge_at(ei, N_EDGES + e);
    if ((unsigned)d < N_NODES) atomicAdd(&g_cnt[d], 1);
}

__global__ void k_scan1() {
    int i = blockIdx.x * 256 + threadIdx.x;
    int lane = threadIdx.x & 31, wid = threadIdx.x >> 5;
    int v = (i < N_NODES) ? g_cnt[i] : 0;
    if (i < N_NODES) g_dinv[i] = rsqrtf((float)v + 1.0f);
    int x = v;
#pragma unroll
    for (int o = 1; o < 32; o <<= 1) {
        int y = __shfl_up_sync(0xffffffffu, x, o);
        if (lane >= o) x += y;
    }
    __shared__ int ws[8];
    if (lane == 31) ws[wid] = x;
    __syncthreads();
    if (wid == 0) {
        int s = (lane < 8) ? ws[lane] : 0;
#pragma unroll
        for (int o = 1; o < 8; o <<= 1) {
            int y = __shfl_up_sync(0xffffffffu, s, o);
            if (lane >= o) s += y;
        }
        if (lane < 8) ws[lane] = s;
    }
    __syncthreads();
    int incl = x + (wid ? ws[wid - 1] : 0);
    if (i < N_NODES) g_off[i] = incl - v;
    if (threadIdx.x == 255) g_bsum[blockIdx.x] = incl;
}

__global__ void k_scan2() {
    int t = threadIdx.x, lane = t & 31, wid = t >> 5;
    int v = (t < NB_SCAN) ? g_bsum[t] : 0;
    int x = v;
#pragma unroll
    for (int o = 1; o < 32; o <<= 1) {
        int y = __shfl_up_sync(0xffffffffu, x, o);
        if (lane >= o) x += y;
    }
    __shared__ int ws[16];
    if (lane == 31) ws[wid] = x;
    __syncthreads();
    if (wid == 0) {
        int s = (lane < 16) ? ws[lane] : 0;
#pragma unroll
        for (int o = 1; o < 16; o <<= 1) {
            int y = __shfl_up_sync(0xffffffffu, s, o);
            if (lane >= o) s += y;
        }
        if (lane < 16) ws[lane] = s;
    }
    __syncthreads();
    int incl = x + (wid ? ws[wid - 1] : 0);
    if (t < 512) g_boff[t] = incl - v;
}

__global__ void k_scan3() {
    int i = blockIdx.x * blockDim.x + threadIdx.x;
    if (i < N_NODES) {
        int o = g_off[i] + g_boff[i >> 8];
        g_off[i] = o;
        g_cur[i] = o;
    }
    if (i == 0) g_off[N_NODES] = N_EDGES;
}

__global__ void k_fill(const void* __restrict__ ei) {
    int e = blockIdx.x * blockDim.x + threadIdx.x;
    if (e >= N_EDGES) return;
    int s = edge_at(ei, e);
    int d = edge_at(ei, N_EDGES + e);
    if ((unsigned)d >= N_NODES || (unsigned)s >= N_NODES) return;
    int p = atomicAdd(&g_cur[d], 1);
    if ((unsigned)p < N_EDGES) g_srcl[p] = s;
}

// ---------------------------------------------------------------------------
// 3xTF32 tensor-core GEMM: Y[n,FOUT] = X[n,64] @ W[64,FOUT]
// block 256 thr (8 warps), tile 128 rows; warp computes 16 rows x FOUT cols.
// mma.m16n8k8 tf32; D = Ahi*Whi + Alo*Whi + Ahi*Wlo  (fp32-grade accuracy).
// ---------------------------------------------------------------------------
__device__ __forceinline__ uint32_t f2tf32(float f) {
    uint32_t r;
    asm("cvt.rna.tf32.f32 %0, %1;" : "=r"(r) : "f"(f));
    return r;
}

__device__ __forceinline__ void mma_tf32(float* c, uint32_t a0, uint32_t a1,
                                         uint32_t a2, uint32_t a3,
                                         uint32_t b0, uint32_t b1) {
    asm volatile(
        "mma.sync.aligned.m16n8k8.row.col.f32.tf32.tf32.f32 "
        "{%0,%1,%2,%3}, {%4,%5,%6,%7}, {%8,%9}, {%0,%1,%2,%3};"
        : "+f"(c[0]), "+f"(c[1]), "+f"(c[2]), "+f"(c[3])
        : "r"(a0), "r"(a1), "r"(a2), "r"(a3), "r"(b0), "r"(b1));
}

template <int FOUT, int WS>
__device__ __forceinline__ void gemm_tf32_body(const float* __restrict__ X,
                                               const float* __restrict__ W,
                                               float* __restrict__ Y) {
    extern __shared__ float sm[];
    float*    xs  = sm;                                 // [128][68]
    uint32_t* whi = (uint32_t*)(sm + 128 * 68);         // [64][WS]
    uint32_t* wlo = whi + 64 * WS;                      // [64][WS]
    const int NT = FOUT / 8;
    int tid = threadIdx.x;
    int warp = tid >> 5, lane = tid & 31;
    int row0 = blockIdx.x * 128;

    // W -> tf32 hi/lo in smem
    for (int idx = tid; idx < 64 * FOUT; idx += 256) {
        int k = idx / FOUT, n = idx % FOUT;
        float w = W[idx];
        uint32_t hi = f2tf32(w);
        float lof = w - __uint_as_float(hi);
        whi[k * WS + n] = hi;
        wlo[k * WS + n] = f2tf32(lof);
    }
    // X tile -> smem (row-major, stride 68), coalesced float4 loads
    for (int idx = tid; idx < 128 * 16; idx += 256) {
        int r = idx >> 4, c4 = idx & 15;
        int gr = row0 + r;
        float4 v = make_float4(0.f, 0.f, 0.f, 0.f);
        if (gr < N_NODES) v = *(const float4*)&X[gr * 64 + c4 * 4];
        float* p = &xs[r * 68 + c4 * 4];
        p[0] = v.x; p[1] = v.y; p[2] = v.z; p[3] = v.w;
    }
    __syncthreads();

    float acc[NT][4];
#pragma unroll
    for (int j = 0; j < NT; j++)
#pragma unroll
        for (int q = 0; q < 4; q++) acc[j][q] = 0.f;

    int rA = warp * 16 + (lane >> 2);     // A frag row (lo half)
    int cA = lane & 3;                    // A frag col within k-step
#pragma unroll
    for (int k8 = 0; k8 < 8; k8++) {
        int kc = k8 * 8 + cA;
        float af0 = xs[rA * 68 + kc];
        float af1 = xs[(rA + 8) * 68 + kc];
        float af2 = xs[rA * 68 + kc + 4];
        float af3 = xs[(rA + 8) * 68 + kc + 4];
        uint32_t ah0 = f2tf32(af0), ah1 = f2tf32(af1);
        uint32_t ah2 = f2tf32(af2), ah3 = f2tf32(af3);
        uint32_t al0 = f2tf32(af0 - __uint_as_float(ah0));
        uint32_t al1 = f2tf32(af1 - __uint_as_float(ah1));
        uint32_t al2 = f2tf32(af2 - __uint_as_float(ah2));
        uint32_t al3 = f2tf32(af3 - __uint_as_float(ah3));

        int br = k8 * 8 + (lane & 3);     // B frag k (lo half)
        int bc = lane >> 2;               // B frag n within j-tile
#pragma unroll
        for (int j = 0; j < NT; j++) {
            int n = j * 8 + bc;
            uint32_t bh0 = whi[br * WS + n];
            uint32_t bh1 = whi[(br + 4) * WS + n];
            uint32_t bl0 = wlo[br * WS + n];
            uint32_t bl1 = wlo[(br + 4) * WS + n];
            mma_tf32(acc[j], ah0, ah1, ah2, ah3, bh0, bh1);
            mma_tf32(acc[j], al0, al1, al2, al3, bh0, bh1);
            mma_tf32(acc[j], ah0, ah1, ah2, ah3, bl0, bl1);
        }
    }

    // store D frags
    int rowLo = row0 + warp * 16 + (lane >> 2);
    int rowHi = rowLo + 8;
    int colB  = (lane & 3) * 2;
#pragma unroll
    for (int j = 0; j < NT; j++) {
        int c = j * 8 + colB;
        if (rowLo < N_NODES) {
            Y[rowLo * FOUT + c]     = acc[j][0];
            Y[rowLo * FOUT + c + 1] = acc[j][1];
        }
        if (rowHi < N_NODES) {
            Y[rowHi * FOUT + c]     = acc[j][2];
            Y[rowHi * FOUT + c + 1] = acc[j][3];
        }
    }
}

// wrappers bind device symbols from DEVICE code (avoid host-decay/ATS bug)
__global__ void k_gemm1(const float* __restrict__ X, const float* __restrict__ W) {
    gemm_tf32_body<64, 68>(X, W, g_h1);
}
__global__ void k_gemm2(const float* __restrict__ W) {
    gemm_tf32_body<40, 44>(g_hid, W, g_h2);
}

// ---------------------------------------------------------------------------
// layer-1 gather: warp per node, 2-edge unroll, dual accumulator chains.
// hid = relu(sum h1[s]*norm + h1[n]*d2 + b1)
// ---------------------------------------------------------------------------
__global__ void k_gather1(const float* __restrict__ b1) {
    int node = (blockIdx.x * blockDim.x + threadIdx.x) >> 5;
    int lane = threadIdx.x & 31;
    if (node >= N_NODES) return;
    float di = g_dinv[node];
    float d2 = di * di;
    float2 hv = *(const float2*)&g_h1[node * 64 + lane * 2];
    float ax = hv.x * d2, ay = hv.y * d2;
    float bx = 0.f, by = 0.f;
    int beg = g_off[node], end = g_off[node + 1];
    int p = beg;
    for (; p + 2 <= end; p += 2) {
        int s0 = g_srcl[p], s1 = g_srcl[p + 1];
        float n0 = g_dinv[s0] * di, n1 = g_dinv[s1] * di;
        float2 v0 = *(const float2*)&g_h1[s0 * 64 + lane * 2];
        float2 v1 = *(const float2*)&g_h1[s1 * 64 + lane * 2];
        ax = fmaf(v0.x, n0, ax); ay = fmaf(v0.y, n0, ay);
        bx = fmaf(v1.x, n1, bx); by = fmaf(v1.y, n1, by);
    }
    if (p < end) {
        int s = g_srcl[p];
        float n = g_dinv[s] * di;
        float2 v = *(const float2*)&g_h1[s * 64 + lane * 2];
        ax = fmaf(v.x, n, ax); ay = fmaf(v.y, n, ay);
    }
    ax += bx; ay += by;
    float2 bv = ((const float2*)b1)[lane];
    ax = fmaxf(ax + bv.x, 0.f);
    ay = fmaxf(ay + bv.y, 0.f);
    *(float2*)&g_hid[node * 64 + lane * 2] = make_float2(ax, ay);
}

// ---------------------------------------------------------------------------
// layer-2 gather + bias + log_softmax: warp per node (lanes 0..19 active)
// ---------------------------------------------------------------------------
__global__ void k_gather2(const float* __restrict__ b2, float* __restrict__ out) {
    int node = (blockIdx.x * blockDim.x + threadIdx.x) >> 5;
    int lane = threadIdx.x & 31;
    if (node >= N_NODES) return;
    float di = g_dinv[node];
    float d2 = di * di;
    int cl = (lane < 20) ? lane : 19;
    bool act = lane < 20;
    float2 hv = *(const float2*)&g_h2[node * 40 + cl * 2];
    float ax = hv.x * d2, ay = hv.y * d2;
    float bx = 0.f, by = 0.f;
    int beg = g_off[node], end = g_off[node + 1];
    int p = beg;
    for (; p + 2 <= end; p += 2) {
        int s0 = g_srcl[p], s1 = g_srcl[p + 1];
        float n0 = g_dinv[s0] * di, n1 = g_dinv[s1] * di;
        float2 v0 = *(const float2*)&g_h2[s0 * 40 + cl * 2];
        float2 v1 = *(const float2*)&g_h2[s1 * 40 + cl * 2];
        ax = fmaf(v0.x, n0, ax); ay = fmaf(v0.y, n0, ay);
        bx = fmaf(v1.x, n1, bx); by = fmaf(v1.y, n1, by);
    }
    if (p < end) {
        int s = g_srcl[p];
        float n = g_dinv[s] * di;
        float2 v = *(const float2*)&g_h2[s * 40 + cl * 2];
        ax = fmaf(v.x, n, ax); ay = fmaf(v.y, n, ay);
    }
    ax += bx; ay += by;
    float2 bv = ((const float2*)b2)[cl];
    ax += bv.x; ay += bv.y;
    float m = act ? fmaxf(ax, ay) : -INFINITY;
#pragma unroll
    for (int o = 16; o; o >>= 1) m = fmaxf(m, __shfl_xor_sync(0xffffffffu, m, o));
    float s = act ? (__expf(ax - m) + __expf(ay - m)) : 0.f;
#pragma unroll
    for (int o = 16; o; o >>= 1) s += __shfl_xor_sync(0xffffffffu, s, o);
    float ls = m + logf(s);
    if (act) *(float2*)&out[node * 40 + lane * 2] = make_float2(ax - ls, ay - ls);
}

// ---------------------------------------------------------------------------
// launch
// ---------------------------------------------------------------------------
extern "C" void kernel_launch(void* const* d_in, const int* in_sizes, int n_in,
                              void* d_out, int out_size) {
    const float* x  = (const float*)d_in[0];
    const void*  ei = d_in[1];
    const float* W1 = (const float*)d_in[2];
    const float* b1 = (const float*)d_in[3];
    const float* W2 = (const float*)d_in[4];
    const float* b2 = (const float*)d_in[5];
    float*       out = (float*)d_out;

    const int SMEM1 = (128 * 68 + 2 * 64 * 68) * 4;   // 69,632 B
    const int SMEM2 = (128 * 68 + 2 * 64 * 44) * 4;   // 57,344 B
    static bool attr_done = false;
    if (!attr_done) {
        cudaFuncSetAttribute(k_gemm1, cudaFuncAttributeMaxDynamicSharedMemorySize, SMEM1);
        cudaFuncSetAttribute(k_gemm2, cudaFuncAttributeMaxDynamicSharedMemorySize, SMEM2);
        attr_done = true;
    }

    const int TB = 256;
    k_init<<<(N_NODES + TB - 1) / TB, TB>>>((const unsigned*)ei);
    k_count<<<(N_EDGES + TB - 1) / TB, TB>>>(ei);
    k_scan1<<<NB_SCAN, 256>>>();
    k_scan2<<<1, 512>>>();
    k_scan3<<<(N_NODES + TB - 1) / TB, TB>>>();
    k_fill<<<(N_EDGES + TB - 1) / TB, TB>>>(ei);
    // layer 1
    k_gemm1<<<(N_NODES + 127) / 128, 256, SMEM1>>>(x, W1);
    k_gather1<<<(N_NODES * 32 + TB - 1) / TB, TB>>>(b1);
    // layer 2
    k_gemm2<<<(N_NODES + 127) / 128, 256, SMEM2>>>(W2);
    k_gather2<<<(N_NODES * 32 + TB - 1) / TB, TB>>>(b2, out);
}

// round 11
// speedup vs baseline: 1.0506x; 1.0506x over previous
#include <cuda_runtime.h>
#include <math.h>

#define N_NODES 100000
#define N_EDGES 800000
#define NB_SCAN ((N_NODES + 255) / 256)   // 391

// ---- static device scratch (no allocations allowed) ----
__device__ int   g_is32;                 // 1 if edge_index delivered as int32
__device__ int   g_cnt [N_NODES];
__device__ int   g_off [N_NODES];        // block-local exclusive prefix
__device__ int   g_cur [N_NODES];        // per-dst bump counters (zeroed in k_init)
__device__ int   g_srcl[N_EDGES];        // sources grouped by dst (CSR)
__device__ float g_dinv[N_NODES];
__device__ float g_h1  [N_NODES * 64];   // layer-1 pre-agg features
__device__ float g_hid [N_NODES * 64];   // relu'd hidden (layer-2 input)
__device__ float g_h2  [N_NODES * 40];   // layer-2 pre-agg features
__device__ int   g_bsum[512];
__device__ int   g_boff[512];            // per-256-block base offsets

// off(i) = g_off[i] + g_boff[i>>8]; off(N_NODES) = N_EDGES
__device__ __forceinline__ int node_off(int i) {
    return (i < N_NODES) ? (g_off[i] + g_boff[i >> 8]) : N_EDGES;
}

// ---------------------------------------------------------------------------
// zero counters/cursors + dtype detection (int64 values < 2^31 -> hi words 0)
// ---------------------------------------------------------------------------
__global__ void k_init(const unsigned* __restrict__ ei_raw) {
    int i = blockIdx.x * blockDim.x + threadIdx.x;
    if (i < N_NODES) { g_cnt[i] = 0; g_cur[i] = 0; }
    if (blockIdx.x == 0 && threadIdx.x < 32) {
        unsigned v = ei_raw[2 * threadIdx.x + 1];
#pragma unroll
        for (int o = 16; o; o >>= 1) v |= __shfl_xor_sync(0xffffffffu, v, o);
        if (threadIdx.x == 0) g_is32 = (v != 0) ? 1 : 0;
    }
}

__device__ __forceinline__ int edge_at(const void* ei, int idx) {
    if (g_is32) return ((const int*)ei)[idx];
    return (int)((const long long*)ei)[idx];
}

// ---------------------------------------------------------------------------
// CSR build
// ---------------------------------------------------------------------------
__global__ void k_count(const void* __restrict__ ei) {
    int e = blockIdx.x * blockDim.x + threadIdx.x;
    if (e >= N_EDGES) return;
    int d = edge_at(ei, N_EDGES + e);
    if ((unsigned)d < N_NODES) atomicAdd(&g_cnt[d], 1);
}

// level-1 scan: 256 nodes per block; also computes dinv
__global__ void k_scan1() {
    int i = blockIdx.x * 256 + threadIdx.x;
    int lane = threadIdx.x & 31, wid = threadIdx.x >> 5;
    int v = (i < N_NODES) ? g_cnt[i] : 0;
    if (i < N_NODES) g_dinv[i] = rsqrtf((float)v + 1.0f);
    int x = v;
#pragma unroll
    for (int o = 1; o < 32; o <<= 1) {
        int y = __shfl_up_sync(0xffffffffu, x, o);
        if (lane >= o) x += y;
    }
    __shared__ int ws[8];
    if (lane == 31) ws[wid] = x;
    __syncthreads();
    if (wid == 0) {
        int s = (lane < 8) ? ws[lane] : 0;
#pragma unroll
        for (int o = 1; o < 8; o <<= 1) {
            int y = __shfl_up_sync(0xffffffffu, s, o);
            if (lane >= o) s += y;
        }
        if (lane < 8) ws[lane] = s;
    }
    __syncthreads();
    int incl = x + (wid ? ws[wid - 1] : 0);
    if (i < N_NODES) g_off[i] = incl - v;
    if (threadIdx.x == 255) g_bsum[blockIdx.x] = incl;
}

// level-2 scan: single block over block sums -> per-block bases
__global__ void k_scan2() {
    int t = threadIdx.x, lane = t & 31, wid = t >> 5;
    int v = (t < NB_SCAN) ? g_bsum[t] : 0;
    int x = v;
#pragma unroll
    for (int o = 1; o < 32; o <<= 1) {
        int y = __shfl_up_sync(0xffffffffu, x, o);
        if (lane >= o) x += y;
    }
    __shared__ int ws[16];
    if (lane == 31) ws[wid] = x;
    __syncthreads();
    if (wid == 0) {
        int s = (lane < 16) ? ws[lane] : 0;
#pragma unroll
        for (int o = 1; o < 16; o <<= 1) {
            int y = __shfl_up_sync(0xffffffffu, s, o);
            if (lane >= o) s += y;
        }
        if (lane < 16) ws[lane] = s;
    }
    __syncthreads();
    int incl = x + (wid ? ws[wid - 1] : 0);
    if (t < 512) g_boff[t] = incl - v;
}

__global__ void k_fill(const void* __restrict__ ei) {
    int e = blockIdx.x * blockDim.x + threadIdx.x;
    if (e >= N_EDGES) return;
    int s = edge_at(ei, e);
    int d = edge_at(ei, N_EDGES + e);
    if ((unsigned)d >= N_NODES || (unsigned)s >= N_NODES) return;
    int p = g_off[d] + g_boff[d >> 8] + atomicAdd(&g_cur[d], 1);
    if ((unsigned)p < N_EDGES) g_srcl[p] = s;
}

// ---------------------------------------------------------------------------
// GEMM body: Y[n,FOUT] = X[n,64] @ W[64,FOUT]  (fp32 SIMT, R7-proven)
// TROWS-row tile, block (FOUT/4, TROWS/8), thread computes 8 rows x 4 cols.
// X/Y bound via device-code symbol references (wrapper kernels) — never
// host-decayed __device__ pointers (ATS silently writes host memory).
// ---------------------------------------------------------------------------
template <int FOUT, int TROWS>
__device__ __forceinline__ void gemm_body(const float* __restrict__ X,
                                          const float* __restrict__ W,
                                          float* __restrict__ Y) {
    __shared__ float ws[64][FOUT];
    __shared__ float xs[64][TROWS + 4];
    const int NT = (FOUT / 4) * (TROWS / 8);
    int tx = threadIdx.x, ty = threadIdx.y;
    int tid = ty * (FOUT / 4) + tx;
    int row0 = blockIdx.x * TROWS;

    for (int idx = tid; idx < 64 * (FOUT / 4); idx += NT) {
        int k = idx / (FOUT / 4), j4 = idx % (FOUT / 4);
        *(float4*)&ws[k][j4 * 4] = *(const float4*)&W[k * FOUT + j4 * 4];
    }
    for (int idx = tid; idx < TROWS * 16; idx += NT) {
        int r = idx & (TROWS - 1), c4 = idx / TROWS;
        int gr = row0 + r;
        float4 v = make_float4(0.f, 0.f, 0.f, 0.f);
        if (gr < N_NODES) v = *(const float4*)&X[gr * 64 + c4 * 4];
        xs[c4 * 4 + 0][r] = v.x; xs[c4 * 4 + 1][r] = v.y;
        xs[c4 * 4 + 2][r] = v.z; xs[c4 * 4 + 3][r] = v.w;
    }
    __syncthreads();

    float acc[8][4];
#pragma unroll
    for (int i = 0; i < 8; i++)
#pragma unroll
        for (int j = 0; j < 4; j++) acc[i][j] = 0.f;

    int rbase = ty * 8;
#pragma unroll 8
    for (int k = 0; k < 64; k++) {
        float4 b  = *(const float4*)&ws[k][tx * 4];
        float4 a0 = *(const float4*)&xs[k][rbase];
        float4 a1 = *(const float4*)&xs[k][rbase + 4];
        float a[8] = {a0.x, a0.y, a0.z, a0.w, a1.x, a1.y, a1.z, a1.w};
#pragma unroll
        for (int i = 0; i < 8; i++) {
            acc[i][0] = fmaf(a[i], b.x, acc[i][0]);
            acc[i][1] = fmaf(a[i], b.y, acc[i][1]);
            acc[i][2] = fmaf(a[i], b.z, acc[i][2]);
            acc[i][3] = fmaf(a[i], b.w, acc[i][3]);
        }
    }

#pragma unroll
    for (int i = 0; i < 8; i++) {
        int gr = row0 + rbase + i;
        if (gr < N_NODES)
            *(float4*)&Y[gr * FOUT + tx * 4] =
                make_float4(acc[i][0], acc[i][1], acc[i][2], acc[i][3]);
    }
}

__global__ void k_gemm1(const float* __restrict__ X, const float* __restrict__ W) {
    gemm_body<64, 64>(X, W, g_h1);
}
__global__ void k_gemm2(const float* __restrict__ W) {
    gemm_body<40, 128>(g_hid, W, g_h2);
}

// ---------------------------------------------------------------------------
// layer-1 gather: warp per node, 2-edge unroll, dual accumulator chains.
// hid = relu(sum h1[s]*norm + h1[n]*d2 + b1)
// ---------------------------------------------------------------------------
__global__ void k_gather1(const float* __restrict__ b1) {
    int node = (blockIdx.x * blockDim.x + threadIdx.x) >> 5;
    int lane = threadIdx.x & 31;
    if (node >= N_NODES) return;
    float di = g_dinv[node];
    float d2 = di * di;
    float2 hv = *(const float2*)&g_h1[node * 64 + lane * 2];
    float ax = hv.x * d2, ay = hv.y * d2;
    float bx = 0.f, by = 0.f;
    int beg = node_off(node), end = node_off(node + 1);
    int p = beg;
    for (; p + 2 <= end; p += 2) {
        int s0 = g_srcl[p], s1 = g_srcl[p + 1];
        float n0 = g_dinv[s0] * di, n1 = g_dinv[s1] * di;
        float2 v0 = *(const float2*)&g_h1[s0 * 64 + lane * 2];
        float2 v1 = *(const float2*)&g_h1[s1 * 64 + lane * 2];
        ax = fmaf(v0.x, n0, ax); ay = fmaf(v0.y, n0, ay);
        bx = fmaf(v1.x, n1, bx); by = fmaf(v1.y, n1, by);
    }
    if (p < end) {
        int s = g_srcl[p];
        float n = g_dinv[s] * di;
        float2 v = *(const float2*)&g_h1[s * 64 + lane * 2];
        ax = fmaf(v.x, n, ax); ay = fmaf(v.y, n, ay);
    }
    ax += bx; ay += by;
    float2 bv = ((const float2*)b1)[lane];
    ax = fmaxf(ax + bv.x, 0.f);
    ay = fmaxf(ay + bv.y, 0.f);
    *(float2*)&g_hid[node * 64 + lane * 2] = make_float2(ax, ay);
}

// ---------------------------------------------------------------------------
// layer-2 gather + bias + log_softmax: warp per node (lanes 0..19 active)
// ---------------------------------------------------------------------------
__global__ void k_gather2(const float* __restrict__ b2, float* __restrict__ out) {
    int node = (blockIdx.x * blockDim.x + threadIdx.x) >> 5;
    int lane = threadIdx.x & 31;
    if (node >= N_NODES) return;
    float di = g_dinv[node];
    float d2 = di * di;
    int cl = (lane < 20) ? lane : 19;
    bool act = lane < 20;
    float2 hv = *(const float2*)&g_h2[node * 40 + cl * 2];
    float ax = hv.x * d2, ay = hv.y * d2;
    float bx = 0.f, by = 0.f;
    int beg = node_off(node), end = node_off(node + 1);
    int p = beg;
    for (; p + 2 <= end; p += 2) {
        int s0 = g_srcl[p], s1 = g_srcl[p + 1];
        float n0 = g_dinv[s0] * di, n1 = g_dinv[s1] * di;
        float2 v0 = *(const float2*)&g_h2[s0 * 40 + cl * 2];
        float2 v1 = *(const float2*)&g_h2[s1 * 40 + cl * 2];
        ax = fmaf(v0.x, n0, ax); ay = fmaf(v0.y, n0, ay);
        bx = fmaf(v1.x, n1, bx); by = fmaf(v1.y, n1, by);
    }
    if (p < end) {
        int s = g_srcl[p];
        float n = g_dinv[s] * di;
        float2 v = *(const float2*)&g_h2[s * 40 + cl * 2];
        ax = fmaf(v.x, n, ax); ay = fmaf(v.y, n, ay);
    }
    ax += bx; ay += by;
    float2 bv = ((const float2*)b2)[cl];
    ax += bv.x; ay += bv.y;
    float m = act ? fmaxf(ax, ay) : -INFINITY;
#pragma unroll
    for (int o = 16; o; o >>= 1) m = fmaxf(m, __shfl_xor_sync(0xffffffffu, m, o));
    float s = act ? (__expf(ax - m) + __expf(ay - m)) : 0.f;
#pragma unroll
    for (int o = 16; o; o >>= 1) s += __shfl_xor_sync(0xffffffffu, s, o);
    float ls = m + logf(s);
    if (act) *(float2*)&out[node * 40 + lane * 2] = make_float2(ax - ls, ay - ls);
}

// ---------------------------------------------------------------------------
// launch: fork-join capture — gemm1 (depends only on inputs) runs on a side
// stream concurrently with the CSR build chain; join before gather1.
// Streams/events are created on the FIRST call (correctness run), so nothing
// is created during graph capture.
// ---------------------------------------------------------------------------
extern "C" void kernel_launch(void* const* d_in, const int* in_sizes, int n_in,
                              void* d_out, int out_size) {
    const float* x  = (const float*)d_in[0];
    const void*  ei = d_in[1];
    const float* W1 = (const float*)d_in[2];
    const float* b1 = (const float*)d_in[3];
    const float* W2 = (const float*)d_in[4];
    const float* b2 = (const float*)d_in[5];
    float*       out = (float*)d_out;

    static cudaStream_t s2 = nullptr;
    static cudaEvent_t  evFork = nullptr, evJoin = nullptr;
    if (s2 == nullptr) {
        cudaStreamCreateWithFlags(&s2, cudaStreamNonBlocking);
        cudaEventCreateWithFlags(&evFork, cudaEventDisableTiming);
        cudaEventCreateWithFlags(&evJoin, cudaEventDisableTiming);
    }

    const int TB = 256;
    // fork: gemm1 on side stream (only reads x, W1)
    cudaEventRecord(evFork, 0);
    cudaStreamWaitEvent(s2, evFork, 0);
    k_gemm1<<<(N_NODES + 63) / 64, dim3(16, 8), 0, s2>>>(x, W1);
    cudaEventRecord(evJoin, s2);

    // main stream: CSR build chain
    k_init<<<(N_NODES + TB - 1) / TB, TB>>>((const unsigned*)ei);
    k_count<<<(N_EDGES + TB - 1) / TB, TB>>>(ei);
    k_scan1<<<NB_SCAN, 256>>>();
    k_scan2<<<1, 512>>>();
    k_fill<<<(N_EDGES + TB - 1) / TB, TB>>>(ei);

    // join: gather1 needs CSR + h1
    cudaStreamWaitEvent(0, evJoin, 0);
    k_gather1<<<(N_NODES * 32 + TB - 1) / TB, TB>>>(b1);
    // layer 2
    k_gemm2<<<(N_NODES + 127) / 128, dim3(10, 16)>>>(W2);
    k_gather2<<<(N_NODES * 32 + TB - 1) / TB, TB>>>(b2, out);
}